// round 1
// baseline (speedup 1.0000x reference)
#include <cuda_runtime.h>
#include <math.h>

#define BB 16
#define NN 4096
#define SS 1024
#define KK 32
#define NTOT (BB*SS*KK)   /* 524288 positions */

// ---------------- scratch (static device globals; no runtime allocation) ---
__device__ float  d_grouped[(size_t)NTOT*6];          // 12.6 MB
__device__ float  d_y[(size_t)NTOT*64];               // 134 MB (y1, then in-place y2)
__device__ float  d_y3[(size_t)NTOT*128];             // 268 MB
__device__ double d_sum[3][128];
__device__ double d_ssq[3][128];
__device__ float  d_nmean[3][128];
__device__ float  d_nscale[3][128];
__device__ float  d_nbeta[3][128];

// ---------------- zero stats (re-run every graph replay) -------------------
__global__ void k_zero() {
    int t = threadIdx.x;
    if (t < 128) {
        #pragma unroll
        for (int l = 0; l < 3; l++) { d_sum[l][t] = 0.0; d_ssq[l][t] = 0.0; }
    }
}

// ---------------- FPS: one block per batch ---------------------------------
// Replicates jax scan: emit farthest, update dist with that centroid, argmax
// (first-index tie-break, matching jnp.argmax).
__global__ void k_fps(const float* __restrict__ xyz, float* __restrict__ out) {
    int b = blockIdx.x;
    int tid = threadIdx.x;               // 512 threads, 8 points each
    const float* X = xyz + (size_t)b * NN * 3;
    float px[8], py[8], pz[8], dd[8];
    int i0 = tid * 8;
    #pragma unroll
    for (int j = 0; j < 8; j++) {
        px[j] = X[(i0 + j) * 3 + 0];
        py[j] = X[(i0 + j) * 3 + 1];
        pz[j] = X[(i0 + j) * 3 + 2];
        dd[j] = 1e10f;
    }
    __shared__ float sc[3];
    __shared__ int   s_far;
    __shared__ float swv[16];
    __shared__ int   swi[16];
    if (tid == 0) s_far = 0;
    __syncthreads();

    for (int it = 0; it < SS; it++) {
        if (tid == 0) {
            int f = s_far;
            float cx = X[f*3], cy = X[f*3+1], cz = X[f*3+2];
            sc[0] = cx; sc[1] = cy; sc[2] = cz;
            float* o = out + ((size_t)b * SS + it) * 3;
            o[0] = cx; o[1] = cy; o[2] = cz;
        }
        __syncthreads();
        float cx = sc[0], cy = sc[1], cz = sc[2];
        float bv = -1.0f; int bi = 0;
        #pragma unroll
        for (int j = 0; j < 8; j++) {
            float dx = px[j] - cx, dy = py[j] - cy, dz = pz[j] - cz;
            float d = dx*dx + dy*dy + dz*dz;
            if (d < dd[j]) dd[j] = d;
            if (dd[j] > bv) { bv = dd[j]; bi = i0 + j; }   // strict > keeps lowest idx
        }
        #pragma unroll
        for (int off = 16; off; off >>= 1) {
            float ov = __shfl_down_sync(0xffffffffu, bv, off);
            int   oi = __shfl_down_sync(0xffffffffu, bi, off);
            if (ov > bv || (ov == bv && oi < bi)) { bv = ov; bi = oi; }
        }
        if ((tid & 31) == 0) { swv[tid >> 5] = bv; swi[tid >> 5] = bi; }
        __syncthreads();
        if (tid == 0) {
            float mv = swv[0]; int mi = swi[0];
            #pragma unroll
            for (int w = 1; w < 16; w++)
                if (swv[w] > mv || (swv[w] == mv && swi[w] < mi)) { mv = swv[w]; mi = swi[w]; }
            s_far = mi;
        }
        // next iteration's leading barrier orders s_far/sc for everyone
    }
}

// ---------------- ball query + grouping: one warp per centroid -------------
// Exact semantics of reference: sqrd = (|s|^2 + |d|^2) - 2*dot ; keep first 32
// in-radius indices in ascending index order; pad with the first member.
__global__ void k_group(const float* __restrict__ xyz,
                        const float* __restrict__ pts,
                        const float* __restrict__ nxyz) {
    int gw = (blockIdx.x * blockDim.x + threadIdx.x) >> 5;
    int lane = threadIdx.x & 31;
    if (gw >= BB * SS) return;
    int b = gw >> 10;
    const float* X = xyz + (size_t)b * NN * 3;
    const float* P = pts + (size_t)b * NN * 3;
    const float* c = nxyz + (size_t)gw * 3;
    float cx = c[0], cy = c[1], cz = c[2];
    float s2 = cx*cx + cy*cy + cz*cz;
    float* G = d_grouped + (size_t)gw * KK * 6;

    int count = 0, firstIdx = 0;
    bool haveFirst = false;
    for (int ch = 0; ch < NN / 32 && count < KK; ch++) {
        int pi = ch * 32 + lane;
        float x = X[pi*3], y = X[pi*3+1], z = X[pi*3+2];
        float d2 = x*x + y*y + z*z;
        float dt = cx*x + cy*y + cz*z;
        float sq = (s2 + d2) - 2.0f * dt;
        bool inside = !(sq > 0.04f);     // float(0.2**2) == 0.04f
        unsigned m = __ballot_sync(0xffffffffu, inside);
        if (!haveFirst && m) { firstIdx = ch * 32 + (__ffs(m) - 1); haveFirst = true; }
        int slot = count + __popc(m & ((1u << lane) - 1u));
        if (inside && slot < KK) {
            float* g = G + slot * 6;
            g[0] = x - cx; g[1] = y - cy; g[2] = z - cz;
            g[3] = P[pi*3]; g[4] = P[pi*3+1]; g[5] = P[pi*3+2];
        }
        count += __popc(m);
    }
    if (count < KK) {
        int fi = firstIdx;   // count >= 1 always (centroid is its own member)
        float x = X[fi*3], y = X[fi*3+1], z = X[fi*3+2];
        float p0 = P[fi*3], p1 = P[fi*3+1], p2 = P[fi*3+2];
        for (int slot = count + lane; slot < KK; slot += 32) {
            float* g = G + slot * 6;
            g[0] = x - cx; g[1] = y - cy; g[2] = z - cz;
            g[3] = p0; g[4] = p1; g[5] = p2;
        }
    }
}

// ---------------- layer 1: 6 -> 64, stats accumulation ---------------------
__global__ void k_layer1(const float* __restrict__ W, const float* __restrict__ Bv) {
    __shared__ __align__(16) float sin_[128 * 6];
    __shared__ float rs[256], rq[256];
    size_t pos0 = (size_t)blockIdx.x * 128;
    int tid = threadIdx.x;
    for (int t = tid; t < 128 * 6; t += 256) sin_[t] = d_grouped[pos0 * 6 + t];
    int c = tid & 63, g = tid >> 6;
    float w[6];
    #pragma unroll
    for (int i = 0; i < 6; i++) w[i] = W[c * 6 + i];
    float bb = Bv[c];
    __syncthreads();
    float ls = 0.f, lq = 0.f;
    for (int p = g; p < 128; p += 4) {
        float acc = bb;
        #pragma unroll
        for (int i = 0; i < 6; i++) acc += w[i] * sin_[p * 6 + i];
        d_y[(pos0 + p) * 64 + c] = acc;
        ls += acc; lq += acc * acc;
    }
    rs[tid] = ls; rq[tid] = lq;
    __syncthreads();
    if (tid < 64) {
        double S = (double)rs[tid] + rs[tid+64] + rs[tid+128] + rs[tid+192];
        double Q = (double)rq[tid] + rq[tid+64] + rq[tid+128] + rq[tid+192];
        atomicAdd(&d_sum[0][tid], S);
        atomicAdd(&d_ssq[0][tid], Q);
    }
}

// ---------------- finalize per-channel mean / gamma*rstd -------------------
__global__ void k_finalize(int layer, int C, const float* __restrict__ gamma,
                           const float* __restrict__ beta) {
    int c = threadIdx.x;
    if (c < C) {
        double n = (double)NTOT;
        double mean = d_sum[layer][c] / n;
        double var  = d_ssq[layer][c] / n - mean * mean;
        float rstd = rsqrtf((float)var + 1e-5f);
        d_nmean[layer][c]  = (float)mean;
        d_nscale[layer][c] = gamma[c] * rstd;
        d_nbeta[layer][c]  = beta[c];
    }
}

// ---------------- layer 2: 64 -> 64 (in-place on d_y) ----------------------
__global__ void k_layer2(const float* __restrict__ W, const float* __restrict__ Bv) {
    __shared__ __align__(16) float sin_[128 * 64];
    __shared__ float rs[256], rq[256];
    size_t pos0 = (size_t)blockIdx.x * 128;
    int tid = threadIdx.x;
    for (int t = tid; t < 128 * 64; t += 256) {
        int cin = t & 63;
        float v = d_y[pos0 * 64 + t];
        v = (v - d_nmean[0][cin]) * d_nscale[0][cin] + d_nbeta[0][cin];
        sin_[t] = fmaxf(v, 0.f);
    }
    int c = tid & 63, g = tid >> 6;
    float w[64];
    #pragma unroll
    for (int i = 0; i < 64; i++) w[i] = W[c * 64 + i];
    float bb = Bv[c];
    __syncthreads();
    float ls = 0.f, lq = 0.f;
    for (int p = g; p < 128; p += 4) {
        const float4* sp = reinterpret_cast<const float4*>(&sin_[p * 64]);
        float acc = bb;
        #pragma unroll
        for (int i = 0; i < 16; i++) {
            float4 v = sp[i];
            acc += w[4*i]   * v.x;
            acc += w[4*i+1] * v.y;
            acc += w[4*i+2] * v.z;
            acc += w[4*i+3] * v.w;
        }
        d_y[(pos0 + p) * 64 + c] = acc;
        ls += acc; lq += acc * acc;
    }
    rs[tid] = ls; rq[tid] = lq;
    __syncthreads();
    if (tid < 64) {
        double S = (double)rs[tid] + rs[tid+64] + rs[tid+128] + rs[tid+192];
        double Q = (double)rq[tid] + rq[tid+64] + rq[tid+128] + rq[tid+192];
        atomicAdd(&d_sum[1][tid], S);
        atomicAdd(&d_ssq[1][tid], Q);
    }
}

// ---------------- layer 3: 64 -> 128 ---------------------------------------
__global__ void k_layer3(const float* __restrict__ W, const float* __restrict__ Bv) {
    __shared__ __align__(16) float sin_[64 * 64];
    __shared__ float rs[256], rq[256];
    size_t pos0 = (size_t)blockIdx.x * 64;
    int tid = threadIdx.x;
    for (int t = tid; t < 64 * 64; t += 256) {
        int cin = t & 63;
        float v = d_y[pos0 * 64 + t];
        v = (v - d_nmean[1][cin]) * d_nscale[1][cin] + d_nbeta[1][cin];
        sin_[t] = fmaxf(v, 0.f);
    }
    int c = tid & 127, g = tid >> 7;
    float w[64];
    #pragma unroll
    for (int i = 0; i < 64; i++) w[i] = W[c * 64 + i];
    float bb = Bv[c];
    __syncthreads();
    float ls = 0.f, lq = 0.f;
    for (int p = g; p < 64; p += 2) {
        const float4* sp = reinterpret_cast<const float4*>(&sin_[p * 64]);
        float acc = bb;
        #pragma unroll
        for (int i = 0; i < 16; i++) {
            float4 v = sp[i];
            acc += w[4*i]   * v.x;
            acc += w[4*i+1] * v.y;
            acc += w[4*i+2] * v.z;
            acc += w[4*i+3] * v.w;
        }
        d_y3[(pos0 + p) * 128 + c] = acc;
        ls += acc; lq += acc * acc;
    }
    rs[tid] = ls; rq[tid] = lq;
    __syncthreads();
    if (tid < 128) {
        double S = (double)rs[tid] + rs[tid + 128];
        double Q = (double)rq[tid] + rq[tid + 128];
        atomicAdd(&d_sum[2][tid], S);
        atomicAdd(&d_ssq[2][tid], Q);
    }
}

// ---------------- normalize + relu + max over K, write output --------------
__global__ void k_pool(float* __restrict__ out) {
    int bs = blockIdx.x;           // 16384 centroids
    int c  = threadIdx.x;          // 128 channels
    float mean = d_nmean[2][c], sc = d_nscale[2][c], be = d_nbeta[2][c];
    const float* Y = d_y3 + (size_t)bs * KK * 128;
    float m = -INFINITY;
    #pragma unroll 4
    for (int k = 0; k < KK; k++) {
        float v = Y[k * 128 + c];
        v = fmaxf((v - mean) * sc + be, 0.f);
        m = fmaxf(m, v);
    }
    out[(size_t)BB * SS * 3 + (size_t)bs * 128 + c] = m;
}

// ---------------- launch ----------------------------------------------------
extern "C" void kernel_launch(void* const* d_in, const int* in_sizes, int n_in,
                              void* d_out, int out_size) {
    const float* xyz = (const float*)d_in[0];
    const float* pts = (const float*)d_in[1];
    const float* w0  = (const float*)d_in[2];
    const float* b0  = (const float*)d_in[3];
    const float* g0  = (const float*)d_in[4];
    const float* be0 = (const float*)d_in[5];
    const float* w1  = (const float*)d_in[6];
    const float* b1  = (const float*)d_in[7];
    const float* g1  = (const float*)d_in[8];
    const float* be1 = (const float*)d_in[9];
    const float* w2  = (const float*)d_in[10];
    const float* b2  = (const float*)d_in[11];
    const float* g2  = (const float*)d_in[12];
    const float* be2 = (const float*)d_in[13];
    float* out = (float*)d_out;

    k_zero<<<1, 128>>>();
    k_fps<<<BB, 512>>>(xyz, out);                    // writes new_xyz region
    k_group<<<(BB * SS) / 8, 256>>>(xyz, pts, out);  // reads new_xyz from out
    k_layer1<<<NTOT / 128, 256>>>(w0, b0);
    k_finalize<<<1, 128>>>(0, 64, g0, be0);
    k_layer2<<<NTOT / 128, 256>>>(w1, b1);
    k_finalize<<<1, 128>>>(1, 64, g1, be1);
    k_layer3<<<NTOT / 64, 256>>>(w2, b2);
    k_finalize<<<1, 128>>>(2, 128, g2, be2);
    k_pool<<<BB * SS, 128>>>(out);
}

// round 2
// speedup vs baseline: 1.2138x; 1.2138x over previous
#include <cuda_runtime.h>
#include <math.h>

#define BB 16
#define NN 4096
#define SS 1024
#define KK 32
#define NTOT (BB*SS*KK)   /* 524288 positions */

typedef unsigned long long ull;

// ---- packed f32x2 helpers (Blackwell FFMA2 path) ---------------------------
__device__ __forceinline__ ull pack2(float lo, float hi) {
    ull r; asm("mov.b64 %0, {%1, %2};" : "=l"(r) : "f"(lo), "f"(hi)); return r;
}
__device__ __forceinline__ void unpack2(ull v, float& lo, float& hi) {
    asm("mov.b64 {%0, %1}, %2;" : "=f"(lo), "=f"(hi) : "l"(v));
}
__device__ __forceinline__ ull fma2(ull a, ull b, ull c) {
    ull d; asm("fma.rn.f32x2 %0, %1, %2, %3;" : "=l"(d) : "l"(a), "l"(b), "l"(c)); return d;
}
__device__ __forceinline__ ull add2(ull a, ull b) {
    ull d; asm("add.rn.f32x2 %0, %1, %2;" : "=l"(d) : "l"(a), "l"(b)); return d;
}

// ---------------- scratch (static device globals) ---------------------------
__device__ float d_grouped[(size_t)NTOT*6];          // 12.6 MB
__device__ float d_y[(size_t)NTOT*64];               // 134 MB (y1, then in-place y2)
__device__ float d_mx[(size_t)BB*SS*128];            // 8 MB  per-centroid channel max (pre-norm)
__device__ float d_mn[(size_t)BB*SS*128];            // 8 MB  per-centroid channel min (pre-norm)
__device__ float d_ps1[64*4096],  d_pq1[64*4096];
__device__ float d_ps2[64*4096],  d_pq2[64*4096];
__device__ float d_ps3[128*8192], d_pq3[128*8192];
__device__ float d_nmean[3][128];
__device__ float d_nscale[3][128];
__device__ float d_nbeta[3][128];

// ---------------- FPS: one block per batch, 256 threads, 16 pts/thread ------
// value-only max reduce + exact-match index resolve (lowest index tie-break,
// matching jnp.argmax). Distance in the reference's direct (p-c)^2 form.
__global__ void __launch_bounds__(256,1) k_fps(const float* __restrict__ xyz,
                                               float* __restrict__ out) {
    int b = blockIdx.x;
    int tid = threadIdx.x;
    int lane = tid & 31, wid = tid >> 5;
    const float* X = xyz + (size_t)b * NN * 3;
    float px[16], py[16], pz[16], dd[16];
    int i0 = tid * 16;
    #pragma unroll
    for (int j = 0; j < 16; j++) {
        px[j] = X[(i0 + j) * 3 + 0];
        py[j] = X[(i0 + j) * 3 + 1];
        pz[j] = X[(i0 + j) * 3 + 2];
        dd[j] = 1e10f;
    }
    __shared__ float sc[4];
    __shared__ float sgm[8];
    __shared__ int   sfl[8];
    __shared__ int   sfi[8];
    if (tid == 0) {
        float cx = X[0], cy = X[1], cz = X[2];
        sc[0] = cx; sc[1] = cy; sc[2] = cz;
        float* o = out + (size_t)b * SS * 3;
        o[0] = cx; o[1] = cy; o[2] = cz;
    }

    for (int it = 0; it < SS - 1; it++) {
        __syncthreads();                         // A: sc visible
        float cx = sc[0], cy = sc[1], cz = sc[2];
        float bv = -1.0f;
        #pragma unroll
        for (int j = 0; j < 16; j++) {
            float dx = px[j] - cx, dy = py[j] - cy, dz = pz[j] - cz;
            float d = dx*dx + dy*dy + dz*dz;
            dd[j] = fminf(dd[j], d);
            bv = fmaxf(bv, dd[j]);
        }
        #pragma unroll
        for (int off = 16; off; off >>= 1)
            bv = fmaxf(bv, __shfl_xor_sync(0xffffffffu, bv, off));
        if (lane == 0) sgm[wid] = bv;
        __syncthreads();                         // B
        float gm = sgm[0];
        #pragma unroll
        for (int w = 1; w < 8; w++) gm = fmaxf(gm, sgm[w]);
        // index match: smallest j with dd[j]==gm (iterate descending)
        int li = -1;
        #pragma unroll
        for (int j = 15; j >= 0; j--) if (dd[j] == gm) li = i0 + j;
        unsigned m = __ballot_sync(0xffffffffu, li >= 0);
        int src = __ffs(m) - 1;
        int wi = __shfl_sync(0xffffffffu, li, src < 0 ? 0 : src);
        if (lane == 0) { sfl[wid] = (m != 0); sfi[wid] = wi; }
        __syncthreads();                         // C
        if (tid == 0) {
            int mi = 0;
            #pragma unroll
            for (int w = 7; w >= 0; w--) if (sfl[w]) mi = sfi[w];
            float nx = X[mi*3], ny = X[mi*3+1], nz = X[mi*3+2];
            sc[0] = nx; sc[1] = ny; sc[2] = nz;
            float* o = out + ((size_t)b * SS + it + 1) * 3;
            o[0] = nx; o[1] = ny; o[2] = nz;
        }
    }
}

// ---------------- ball query + grouping: one warp per centroid --------------
__global__ void k_group(const float* __restrict__ xyz,
                        const float* __restrict__ pts,
                        const float* __restrict__ nxyz) {
    int gw = (blockIdx.x * blockDim.x + threadIdx.x) >> 5;
    int lane = threadIdx.x & 31;
    if (gw >= BB * SS) return;
    int b = gw >> 10;
    const float* X = xyz + (size_t)b * NN * 3;
    const float* P = pts + (size_t)b * NN * 3;
    const float* c = nxyz + (size_t)gw * 3;
    float cx = c[0], cy = c[1], cz = c[2];
    float s2 = cx*cx + cy*cy + cz*cz;
    float* G = d_grouped + (size_t)gw * KK * 6;

    int count = 0, firstIdx = 0;
    bool haveFirst = false;
    for (int ch = 0; ch < NN / 32 && count < KK; ch++) {
        int pi = ch * 32 + lane;
        float x = X[pi*3], y = X[pi*3+1], z = X[pi*3+2];
        float d2 = x*x + y*y + z*z;
        float dt = cx*x + cy*y + cz*z;
        float sq = (s2 + d2) - 2.0f * dt;
        bool inside = !(sq > 0.04f);
        unsigned m = __ballot_sync(0xffffffffu, inside);
        if (!haveFirst && m) { firstIdx = ch * 32 + (__ffs(m) - 1); haveFirst = true; }
        int slot = count + __popc(m & ((1u << lane) - 1u));
        if (inside && slot < KK) {
            float* g = G + slot * 6;
            g[0] = x - cx; g[1] = y - cy; g[2] = z - cz;
            g[3] = P[pi*3]; g[4] = P[pi*3+1]; g[5] = P[pi*3+2];
        }
        count += __popc(m);
    }
    if (count < KK) {
        int fi = firstIdx;
        float x = X[fi*3], y = X[fi*3+1], z = X[fi*3+2];
        float p0 = P[fi*3], p1 = P[fi*3+1], p2 = P[fi*3+2];
        for (int slot = count + lane; slot < KK; slot += 32) {
            float* g = G + slot * 6;
            g[0] = x - cx; g[1] = y - cy; g[2] = z - cz;
            g[3] = p0; g[4] = p1; g[5] = p2;
        }
    }
}

// ---------------- layer 1: 6 -> 64 ------------------------------------------
__global__ void k_layer1(const float* __restrict__ W, const float* __restrict__ Bv) {
    __shared__ __align__(16) float sin_[128 * 6];
    __shared__ float rs[256], rq[256];
    size_t pos0 = (size_t)blockIdx.x * 128;
    int tid = threadIdx.x;
    for (int t = tid; t < 128 * 6; t += 256) sin_[t] = d_grouped[pos0 * 6 + t];
    int c = tid & 63, g = tid >> 6;
    float w[6];
    #pragma unroll
    for (int i = 0; i < 6; i++) w[i] = W[c * 6 + i];
    float bb = Bv[c];
    __syncthreads();
    float ls = 0.f, lq = 0.f;
    for (int p = g; p < 128; p += 4) {
        float acc = bb;
        #pragma unroll
        for (int i = 0; i < 6; i++) acc += w[i] * sin_[p * 6 + i];
        d_y[(pos0 + p) * 64 + c] = acc;
        ls += acc; lq += acc * acc;
    }
    rs[tid] = ls; rq[tid] = lq;
    __syncthreads();
    if (tid < 64) {
        float S = rs[tid] + rs[tid+64] + rs[tid+128] + rs[tid+192];
        float Q = rq[tid] + rq[tid+64] + rq[tid+128] + rq[tid+192];
        d_ps1[tid * 4096 + blockIdx.x] = S;
        d_pq1[tid * 4096 + blockIdx.x] = Q;
    }
}

// ---------------- finalize: reduce partials, build norm params ---------------
__global__ void k_finalize(int layer, int nblk,
                           const float* __restrict__ gamma,
                           const float* __restrict__ beta) {
    const float* ps = layer == 0 ? d_ps1 : layer == 1 ? d_ps2 : d_ps3;
    const float* pq = layer == 0 ? d_pq1 : layer == 1 ? d_pq2 : d_pq3;
    int c = blockIdx.x;
    __shared__ double sd[256], sq[256];
    double s = 0.0, q = 0.0;
    for (int i = threadIdx.x; i < nblk; i += 256) {
        s += (double)ps[(size_t)c * nblk + i];
        q += (double)pq[(size_t)c * nblk + i];
    }
    sd[threadIdx.x] = s; sq[threadIdx.x] = q;
    __syncthreads();
    for (int off = 128; off; off >>= 1) {
        if (threadIdx.x < off) {
            sd[threadIdx.x] += sd[threadIdx.x + off];
            sq[threadIdx.x] += sq[threadIdx.x + off];
        }
        __syncthreads();
    }
    if (threadIdx.x == 0) {
        double n = (double)NTOT;
        double mean = sd[0] / n;
        double var  = sq[0] / n - mean * mean;
        float rstd = rsqrtf((float)var + 1e-5f);
        d_nmean[layer][c]  = (float)mean;
        d_nscale[layer][c] = gamma[c] * rstd;
        d_nbeta[layer][c]  = beta[c];
    }
}

// ---------------- layer 2: 64 -> 64, FFMA2, pair-interleaved shared ---------
__global__ void __launch_bounds__(256,1) k_layer2(const float* __restrict__ W,
                                                  const float* __restrict__ Bv) {
    __shared__ __align__(16) float s[64 * 128];   // 32KB: [pair q][cin*2 + half]
    __shared__ float rs[256], rq[256];
    size_t pos0 = (size_t)blockIdx.x * 128;
    int tid = threadIdx.x;
    for (int t = tid; t < 128 * 64; t += 256) {
        int p = t >> 6, cin = t & 63;
        float v = d_y[pos0 * 64 + t];
        v = fmaxf((v - d_nmean[0][cin]) * d_nscale[0][cin] + d_nbeta[0][cin], 0.f);
        s[(p >> 1) * 128 + cin * 2 + (p & 1)] = v;
    }
    int c = tid & 63, g = tid >> 6;
    ull w2[64];
    #pragma unroll
    for (int i = 0; i < 64; i++) { float wv = W[c * 64 + i]; w2[i] = pack2(wv, wv); }
    float bb = Bv[c];
    __syncthreads();
    float ls = 0.f, lq = 0.f;
    for (int q = g; q < 64; q += 4) {
        const ulonglong2* sp = (const ulonglong2*)(s + q * 128);
        ull acc_a = pack2(bb, bb), acc_b = pack2(0.f, 0.f);
        #pragma unroll
        for (int i = 0; i < 32; i++) {
            ulonglong2 v = sp[i];
            acc_a = fma2(w2[2*i],   v.x, acc_a);
            acc_b = fma2(w2[2*i+1], v.y, acc_b);
        }
        ull acc = add2(acc_a, acc_b);
        float lo, hi; unpack2(acc, lo, hi);
        d_y[(pos0 + 2*q)     * 64 + c] = lo;
        d_y[(pos0 + 2*q + 1) * 64 + c] = hi;
        ls += lo + hi; lq += lo*lo + hi*hi;
    }
    rs[tid] = ls; rq[tid] = lq;
    __syncthreads();
    if (tid < 64) {
        float S = rs[tid] + rs[tid+64] + rs[tid+128] + rs[tid+192];
        float Q = rq[tid] + rq[tid+64] + rq[tid+128] + rq[tid+192];
        d_ps2[tid * 4096 + blockIdx.x] = S;
        d_pq2[tid * 4096 + blockIdx.x] = Q;
    }
}

// ---------------- layer 3: 64 -> 128, FFMA2, fused max/min pool --------------
__global__ void __launch_bounds__(256,1) k_layer3(const float* __restrict__ W,
                                                  const float* __restrict__ Bv) {
    __shared__ __align__(16) float s[32 * 128];   // 16KB
    __shared__ float rs[256], rq[256];
    __shared__ float smx[2][2][128], smn[2][2][128];
    size_t pos0 = (size_t)blockIdx.x * 64;        // 2 centroids per block
    int tid = threadIdx.x;
    for (int t = tid; t < 64 * 64; t += 256) {
        int p = t >> 6, cin = t & 63;
        float v = d_y[pos0 * 64 + t];
        v = fmaxf((v - d_nmean[1][cin]) * d_nscale[1][cin] + d_nbeta[1][cin], 0.f);
        s[(p >> 1) * 128 + cin * 2 + (p & 1)] = v;
    }
    int c = tid & 127, g = tid >> 7;
    ull w2[64];
    #pragma unroll
    for (int i = 0; i < 64; i++) { float wv = W[c * 64 + i]; w2[i] = pack2(wv, wv); }
    float bb = Bv[c];
    __syncthreads();
    float ls = 0.f, lq = 0.f;
    float mx0 = -INFINITY, mn0 = INFINITY, mx1 = -INFINITY, mn1 = INFINITY;
    for (int q = g; q < 32; q += 2) {
        const ulonglong2* sp = (const ulonglong2*)(s + q * 128);
        ull acc_a = pack2(bb, bb), acc_b = pack2(0.f, 0.f);
        #pragma unroll
        for (int i = 0; i < 32; i++) {
            ulonglong2 v = sp[i];
            acc_a = fma2(w2[2*i],   v.x, acc_a);
            acc_b = fma2(w2[2*i+1], v.y, acc_b);
        }
        ull acc = add2(acc_a, acc_b);
        float lo, hi; unpack2(acc, lo, hi);
        ls += lo + hi; lq += lo*lo + hi*hi;
        float M = fmaxf(lo, hi), m = fminf(lo, hi);
        if (q < 16) { mx0 = fmaxf(mx0, M); mn0 = fminf(mn0, m); }
        else        { mx1 = fmaxf(mx1, M); mn1 = fminf(mn1, m); }
    }
    smx[g][0][c] = mx0; smx[g][1][c] = mx1;
    smn[g][0][c] = mn0; smn[g][1][c] = mn1;
    rs[tid] = ls; rq[tid] = lq;
    __syncthreads();
    {
        int cent = tid >> 7, cc = tid & 127;
        float M = fmaxf(smx[0][cent][cc], smx[1][cent][cc]);
        float m = fminf(smn[0][cent][cc], smn[1][cent][cc]);
        size_t o = (size_t)(blockIdx.x * 2 + cent) * 128 + cc;
        d_mx[o] = M; d_mn[o] = m;
    }
    if (tid < 128) {
        float S = rs[tid] + rs[tid + 128];
        float Q = rq[tid] + rq[tid + 128];
        d_ps3[tid * 8192 + blockIdx.x] = S;
        d_pq3[tid * 8192 + blockIdx.x] = Q;
    }
}

// ---------------- final pool: norm(max-or-min) + relu, write output ----------
__global__ void k_poolf(float* __restrict__ out) {
    int g = blockIdx.x * 256 + threadIdx.x;      // 16384*128 elems
    int c = g & 127;
    float scv = d_nscale[2][c];
    float v = (scv >= 0.f) ? d_mx[g] : d_mn[g];
    out[(size_t)BB * SS * 3 + g] = fmaxf((v - d_nmean[2][c]) * scv + d_nbeta[2][c], 0.f);
}

// ---------------- launch -----------------------------------------------------
extern "C" void kernel_launch(void* const* d_in, const int* in_sizes, int n_in,
                              void* d_out, int out_size) {
    const float* xyz = (const float*)d_in[0];
    const float* pts = (const float*)d_in[1];
    const float* w0  = (const float*)d_in[2];
    const float* b0  = (const float*)d_in[3];
    const float* g0  = (const float*)d_in[4];
    const float* be0 = (const float*)d_in[5];
    const float* w1  = (const float*)d_in[6];
    const float* b1  = (const float*)d_in[7];
    const float* g1  = (const float*)d_in[8];
    const float* be1 = (const float*)d_in[9];
    const float* w2  = (const float*)d_in[10];
    const float* b2  = (const float*)d_in[11];
    const float* g2  = (const float*)d_in[12];
    const float* be2 = (const float*)d_in[13];
    float* out = (float*)d_out;

    k_fps<<<BB, 256>>>(xyz, out);
    k_group<<<(BB * SS) / 8, 256>>>(xyz, pts, out);
    k_layer1<<<NTOT / 128, 256>>>(w0, b0);
    k_finalize<<<64, 256>>>(0, 4096, g0, be0);
    k_layer2<<<NTOT / 128, 256>>>(w1, b1);
    k_finalize<<<64, 256>>>(1, 4096, g1, be1);
    k_layer3<<<NTOT / 64, 256>>>(w2, b2);
    k_finalize<<<128, 256>>>(2, 8192, g2, be2);
    k_poolf<<<(BB * SS * 128) / 256, 256>>>(out);
}

// round 3
// speedup vs baseline: 1.2354x; 1.0178x over previous
#include <cuda_runtime.h>
#include <math.h>

#define BB 16
#define NN 4096
#define SS 1024
#define KK 32
#define NTOT (BB*SS*KK)   /* 524288 positions */

typedef unsigned long long ull;

// ---- packed f32x2 helpers (Blackwell FFMA2 path) ---------------------------
__device__ __forceinline__ ull pack2(float lo, float hi) {
    ull r; asm("mov.b64 %0, {%1, %2};" : "=l"(r) : "f"(lo), "f"(hi)); return r;
}
__device__ __forceinline__ void unpack2(ull v, float& lo, float& hi) {
    asm("mov.b64 {%0, %1}, %2;" : "=f"(lo), "=f"(hi) : "l"(v));
}
__device__ __forceinline__ ull fma2(ull a, ull b, ull c) {
    ull d; asm("fma.rn.f32x2 %0, %1, %2, %3;" : "=l"(d) : "l"(a), "l"(b), "l"(c)); return d;
}
__device__ __forceinline__ ull add2(ull a, ull b) {
    ull d; asm("add.rn.f32x2 %0, %1, %2;" : "=l"(d) : "l"(a), "l"(b)); return d;
}

// ---------------- scratch (static device globals) ---------------------------
__device__ float d_grouped[(size_t)NTOT*6];          // 12.6 MB
__device__ float d_y[(size_t)NTOT*64];               // 134 MB (y1, then in-place y2)
__device__ float d_mx[(size_t)BB*SS*128];            // 8 MB  per-centroid channel max (pre-norm)
__device__ float d_mn[(size_t)BB*SS*128];            // 8 MB  per-centroid channel min (pre-norm)
__device__ float d_ps1[64*4096],  d_pq1[64*4096];
__device__ float d_ps2[64*4096],  d_pq2[64*4096];
__device__ float d_ps3[128*8192], d_pq3[128*8192];
__device__ float d_nmean[3][128];
__device__ float d_nscale[3][128];
__device__ float d_nbeta[3][128];

// ---------------- FPS: one block/batch, 256 thr, 16 pts/thr, ONE barrier/iter
// Argmax with lowest-index tie-break (matches jnp.argmax) via 64-bit key:
//   key = (float_bits(dd) << 32) | (0x1FFFF - idx)    [dd >= 0 -> monotone]
// Per-point arithmetic kept source-identical to the passing R2 kernel.
__global__ void __launch_bounds__(256,1) k_fps(const float* __restrict__ xyz,
                                               float* __restrict__ out) {
    int b = blockIdx.x;
    int tid = threadIdx.x;
    int lane = tid & 31, wid = tid >> 5;
    const float* X = xyz + (size_t)b * NN * 3;
    float px[16], py[16], pz[16], dd[16];
    int i0 = tid * 16;
    #pragma unroll
    for (int j = 0; j < 16; j++) {
        px[j] = X[(i0 + j) * 3 + 0];
        py[j] = X[(i0 + j) * 3 + 1];
        pz[j] = X[(i0 + j) * 3 + 2];
        dd[j] = 1e10f;
    }
    __shared__ ull skey[2][8];
    int w = 0;                                   // current centroid index

    for (int it = 0; it < SS; it++) {
        float cx = __ldg(X + w * 3 + 0);
        float cy = __ldg(X + w * 3 + 1);
        float cz = __ldg(X + w * 3 + 2);
        if (tid == 0) {
            float* o = out + ((size_t)b * SS + it) * 3;
            o[0] = cx; o[1] = cy; o[2] = cz;
        }
        if (it == SS - 1) break;

        float bv = -1.0f;
        #pragma unroll
        for (int j = 0; j < 16; j++) {
            float dx = px[j] - cx, dy = py[j] - cy, dz = pz[j] - cz;
            float d = dx*dx + dy*dy + dz*dz;
            dd[j] = fminf(dd[j], d);
            bv = fmaxf(bv, dd[j]);
        }
        int li = 0;
        #pragma unroll
        for (int j = 15; j >= 0; j--) if (dd[j] == bv) li = i0 + j;  // lowest j wins
        ull key = ((ull)__float_as_uint(bv) << 32) | (unsigned)(0x1FFFF - li);
        #pragma unroll
        for (int off = 16; off; off >>= 1) {
            ull o = __shfl_xor_sync(0xffffffffu, key, off);
            key = (o > key) ? o : key;
        }
        if (lane == 0) skey[it & 1][wid] = key;
        __syncthreads();
        ull k0 = skey[it & 1][0];
        #pragma unroll
        for (int wq = 1; wq < 8; wq++) { ull o = skey[it & 1][wq]; k0 = (o > k0) ? o : k0; }
        w = 0x1FFFF - (int)(k0 & 0xFFFFFFFFull);
    }
}

// ---------------- ball query + grouping: one warp per centroid --------------
__global__ void k_group(const float* __restrict__ xyz,
                        const float* __restrict__ pts,
                        const float* __restrict__ nxyz) {
    int gw = (blockIdx.x * blockDim.x + threadIdx.x) >> 5;
    int lane = threadIdx.x & 31;
    if (gw >= BB * SS) return;
    int b = gw >> 10;
    const float* X = xyz + (size_t)b * NN * 3;
    const float* P = pts + (size_t)b * NN * 3;
    const float* c = nxyz + (size_t)gw * 3;
    float cx = c[0], cy = c[1], cz = c[2];
    float s2 = cx*cx + cy*cy + cz*cz;
    float* G = d_grouped + (size_t)gw * KK * 6;

    int count = 0, firstIdx = 0;
    bool haveFirst = false;
    for (int ch = 0; ch < NN / 32 && count < KK; ch++) {
        int pi = ch * 32 + lane;
        float x = X[pi*3], y = X[pi*3+1], z = X[pi*3+2];
        float d2 = x*x + y*y + z*z;
        float dt = cx*x + cy*y + cz*z;
        float sq = (s2 + d2) - 2.0f * dt;
        bool inside = !(sq > 0.04f);
        unsigned m = __ballot_sync(0xffffffffu, inside);
        if (!haveFirst && m) { firstIdx = ch * 32 + (__ffs(m) - 1); haveFirst = true; }
        int slot = count + __popc(m & ((1u << lane) - 1u));
        if (inside && slot < KK) {
            float* g = G + slot * 6;
            g[0] = x - cx; g[1] = y - cy; g[2] = z - cz;
            g[3] = P[pi*3]; g[4] = P[pi*3+1]; g[5] = P[pi*3+2];
        }
        count += __popc(m);
    }
    if (count < KK) {
        int fi = firstIdx;
        float x = X[fi*3], y = X[fi*3+1], z = X[fi*3+2];
        float p0 = P[fi*3], p1 = P[fi*3+1], p2 = P[fi*3+2];
        for (int slot = count + lane; slot < KK; slot += 32) {
            float* g = G + slot * 6;
            g[0] = x - cx; g[1] = y - cy; g[2] = z - cz;
            g[3] = p0; g[4] = p1; g[5] = p2;
        }
    }
}

// ---------------- layer 1: 6 -> 64 ------------------------------------------
__global__ void k_layer1(const float* __restrict__ W, const float* __restrict__ Bv) {
    __shared__ __align__(16) float sin_[128 * 6];
    __shared__ float rs[256], rq[256];
    size_t pos0 = (size_t)blockIdx.x * 128;
    int tid = threadIdx.x;
    for (int t = tid; t < 128 * 6; t += 256) sin_[t] = d_grouped[pos0 * 6 + t];
    int c = tid & 63, g = tid >> 6;
    float w[6];
    #pragma unroll
    for (int i = 0; i < 6; i++) w[i] = W[c * 6 + i];
    float bb = Bv[c];
    __syncthreads();
    float ls = 0.f, lq = 0.f;
    for (int p = g; p < 128; p += 4) {
        float acc = bb;
        #pragma unroll
        for (int i = 0; i < 6; i++) acc += w[i] * sin_[p * 6 + i];
        d_y[(pos0 + p) * 64 + c] = acc;
        ls += acc; lq += acc * acc;
    }
    rs[tid] = ls; rq[tid] = lq;
    __syncthreads();
    if (tid < 64) {
        float S = rs[tid] + rs[tid+64] + rs[tid+128] + rs[tid+192];
        float Q = rq[tid] + rq[tid+64] + rq[tid+128] + rq[tid+192];
        d_ps1[tid * 4096 + blockIdx.x] = S;
        d_pq1[tid * 4096 + blockIdx.x] = Q;
    }
}

// ---------------- finalize: reduce partials, build norm params ---------------
__global__ void k_finalize(int layer, int nblk,
                           const float* __restrict__ gamma,
                           const float* __restrict__ beta) {
    const float* ps = layer == 0 ? d_ps1 : layer == 1 ? d_ps2 : d_ps3;
    const float* pq = layer == 0 ? d_pq1 : layer == 1 ? d_pq2 : d_pq3;
    int c = blockIdx.x;
    __shared__ double sd[256], sq[256];
    double s = 0.0, q = 0.0;
    for (int i = threadIdx.x; i < nblk; i += 256) {
        s += (double)ps[(size_t)c * nblk + i];
        q += (double)pq[(size_t)c * nblk + i];
    }
    sd[threadIdx.x] = s; sq[threadIdx.x] = q;
    __syncthreads();
    for (int off = 128; off; off >>= 1) {
        if (threadIdx.x < off) {
            sd[threadIdx.x] += sd[threadIdx.x + off];
            sq[threadIdx.x] += sq[threadIdx.x + off];
        }
        __syncthreads();
    }
    if (threadIdx.x == 0) {
        double n = (double)NTOT;
        double mean = sd[0] / n;
        double var  = sq[0] / n - mean * mean;
        float rstd = rsqrtf((float)var + 1e-5f);
        d_nmean[layer][c]  = (float)mean;
        d_nscale[layer][c] = gamma[c] * rstd;
        d_nbeta[layer][c]  = beta[c];
    }
}

// ---------------- layer 2: 64 -> 64, FFMA2, pair-interleaved shared ---------
__global__ void __launch_bounds__(256,1) k_layer2(const float* __restrict__ W,
                                                  const float* __restrict__ Bv) {
    __shared__ __align__(16) float s[64 * 128];   // 32KB: [pair q][cin*2 + half]
    __shared__ float rs[256], rq[256];
    size_t pos0 = (size_t)blockIdx.x * 128;
    int tid = threadIdx.x;
    {
        int cin = tid & 63;                       // invariant across staging loop
        float nm = d_nmean[0][cin], nsc = d_nscale[0][cin], nb = d_nbeta[0][cin];
        for (int t = tid; t < 128 * 64; t += 256) {
            int p = t >> 6;
            float v = d_y[pos0 * 64 + t];
            v = fmaxf((v - nm) * nsc + nb, 0.f);
            s[(p >> 1) * 128 + cin * 2 + (p & 1)] = v;
        }
    }
    int c = tid & 63, g = tid >> 6;
    ull w2[64];
    #pragma unroll
    for (int i = 0; i < 64; i++) { float wv = W[c * 64 + i]; w2[i] = pack2(wv, wv); }
    float bb = Bv[c];
    __syncthreads();
    float ls = 0.f, lq = 0.f;
    for (int q = g; q < 64; q += 4) {
        const ulonglong2* sp = (const ulonglong2*)(s + q * 128);
        ull acc_a = pack2(bb, bb), acc_b = pack2(0.f, 0.f);
        #pragma unroll
        for (int i = 0; i < 32; i++) {
            ulonglong2 v = sp[i];
            acc_a = fma2(w2[2*i],   v.x, acc_a);
            acc_b = fma2(w2[2*i+1], v.y, acc_b);
        }
        ull acc = add2(acc_a, acc_b);
        float lo, hi; unpack2(acc, lo, hi);
        d_y[(pos0 + 2*q)     * 64 + c] = lo;
        d_y[(pos0 + 2*q + 1) * 64 + c] = hi;
        ls += lo + hi; lq += lo*lo + hi*hi;
    }
    rs[tid] = ls; rq[tid] = lq;
    __syncthreads();
    if (tid < 64) {
        float S = rs[tid] + rs[tid+64] + rs[tid+128] + rs[tid+192];
        float Q = rq[tid] + rq[tid+64] + rq[tid+128] + rq[tid+192];
        d_ps2[tid * 4096 + blockIdx.x] = S;
        d_pq2[tid * 4096 + blockIdx.x] = Q;
    }
}

// ---------------- layer 3: 64 -> 128, FFMA2, fused max/min pool --------------
__global__ void __launch_bounds__(256,1) k_layer3(const float* __restrict__ W,
                                                  const float* __restrict__ Bv) {
    __shared__ __align__(16) float s[32 * 128];   // 16KB
    __shared__ float rs[256], rq[256];
    __shared__ float smx[2][2][128], smn[2][2][128];
    size_t pos0 = (size_t)blockIdx.x * 64;        // 2 centroids per block
    int tid = threadIdx.x;
    {
        int cin = tid & 63;
        float nm = d_nmean[1][cin], nsc = d_nscale[1][cin], nb = d_nbeta[1][cin];
        for (int t = tid; t < 64 * 64; t += 256) {
            int p = t >> 6;
            float v = d_y[pos0 * 64 + t];
            v = fmaxf((v - nm) * nsc + nb, 0.f);
            s[(p >> 1) * 128 + cin * 2 + (p & 1)] = v;
        }
    }
    int c = tid & 127, g = tid >> 7;
    ull w2[64];
    #pragma unroll
    for (int i = 0; i < 64; i++) { float wv = W[c * 64 + i]; w2[i] = pack2(wv, wv); }
    float bb = Bv[c];
    __syncthreads();
    float ls = 0.f, lq = 0.f;
    float mx0 = -INFINITY, mn0 = INFINITY, mx1 = -INFINITY, mn1 = INFINITY;
    for (int q = g; q < 32; q += 2) {
        const ulonglong2* sp = (const ulonglong2*)(s + q * 128);
        ull acc_a = pack2(bb, bb), acc_b = pack2(0.f, 0.f);
        #pragma unroll
        for (int i = 0; i < 32; i++) {
            ulonglong2 v = sp[i];
            acc_a = fma2(w2[2*i],   v.x, acc_a);
            acc_b = fma2(w2[2*i+1], v.y, acc_b);
        }
        ull acc = add2(acc_a, acc_b);
        float lo, hi; unpack2(acc, lo, hi);
        ls += lo + hi; lq += lo*lo + hi*hi;
        float M = fmaxf(lo, hi), m = fminf(lo, hi);
        if (q < 16) { mx0 = fmaxf(mx0, M); mn0 = fminf(mn0, m); }
        else        { mx1 = fmaxf(mx1, M); mn1 = fminf(mn1, m); }
    }
    smx[g][0][c] = mx0; smx[g][1][c] = mx1;
    smn[g][0][c] = mn0; smn[g][1][c] = mn1;
    rs[tid] = ls; rq[tid] = lq;
    __syncthreads();
    {
        int cent = tid >> 7, cc = tid & 127;
        float M = fmaxf(smx[0][cent][cc], smx[1][cent][cc]);
        float m = fminf(smn[0][cent][cc], smn[1][cent][cc]);
        size_t o = (size_t)(blockIdx.x * 2 + cent) * 128 + cc;
        d_mx[o] = M; d_mn[o] = m;
    }
    if (tid < 128) {
        float S = rs[tid] + rs[tid + 128];
        float Q = rq[tid] + rq[tid + 128];
        d_ps3[tid * 8192 + blockIdx.x] = S;
        d_pq3[tid * 8192 + blockIdx.x] = Q;
    }
}

// ---------------- final pool: norm(max-or-min) + relu, write output ----------
__global__ void k_poolf(float* __restrict__ out) {
    int g = blockIdx.x * 256 + threadIdx.x;      // 16384*128 elems
    int c = g & 127;
    float scv = d_nscale[2][c];
    float v = (scv >= 0.f) ? d_mx[g] : d_mn[g];
    out[(size_t)BB * SS * 3 + g] = fmaxf((v - d_nmean[2][c]) * scv + d_nbeta[2][c], 0.f);
}

// ---------------- launch -----------------------------------------------------
extern "C" void kernel_launch(void* const* d_in, const int* in_sizes, int n_in,
                              void* d_out, int out_size) {
    const float* xyz = (const float*)d_in[0];
    const float* pts = (const float*)d_in[1];
    const float* w0  = (const float*)d_in[2];
    const float* b0  = (const float*)d_in[3];
    const float* g0  = (const float*)d_in[4];
    const float* be0 = (const float*)d_in[5];
    const float* w1  = (const float*)d_in[6];
    const float* b1  = (const float*)d_in[7];
    const float* g1  = (const float*)d_in[8];
    const float* be1 = (const float*)d_in[9];
    const float* w2  = (const float*)d_in[10];
    const float* b2  = (const float*)d_in[11];
    const float* g2  = (const float*)d_in[12];
    const float* be2 = (const float*)d_in[13];
    float* out = (float*)d_out;

    k_fps<<<BB, 256>>>(xyz, out);
    k_group<<<(BB * SS) / 8, 256>>>(xyz, pts, out);
    k_layer1<<<NTOT / 128, 256>>>(w0, b0);
    k_finalize<<<64, 256>>>(0, 4096, g0, be0);
    k_layer2<<<NTOT / 128, 256>>>(w1, b1);
    k_finalize<<<64, 256>>>(1, 4096, g1, be1);
    k_layer3<<<NTOT / 64, 256>>>(w2, b2);
    k_finalize<<<128, 256>>>(2, 8192, g2, be2);
    k_poolf<<<(BB * SS * 128) / 256, 256>>>(out);
}

// round 5
// speedup vs baseline: 1.2536x; 1.0147x over previous
#include <cuda_runtime.h>
#include <math.h>

#define BB 16
#define NN 4096
#define SS 1024
#define KK 32
#define NTOT (BB*SS*KK)   /* 524288 positions */

typedef unsigned long long ull;

// ---- packed f32x2 helpers (Blackwell FFMA2 path) ---------------------------
__device__ __forceinline__ ull pack2(float lo, float hi) {
    ull r; asm("mov.b64 %0, {%1, %2};" : "=l"(r) : "f"(lo), "f"(hi)); return r;
}
__device__ __forceinline__ void unpack2(ull v, float& lo, float& hi) {
    asm("mov.b64 {%0, %1}, %2;" : "=f"(lo), "=f"(hi) : "l"(v));
}
__device__ __forceinline__ ull fma2(ull a, ull b, ull c) {
    ull d; asm("fma.rn.f32x2 %0, %1, %2, %3;" : "=l"(d) : "l"(a), "l"(b), "l"(c)); return d;
}
__device__ __forceinline__ ull add2(ull a, ull b) {
    ull d; asm("add.rn.f32x2 %0, %1, %2;" : "=l"(d) : "l"(a), "l"(b)); return d;
}

// ---------------- scratch (static device globals) ---------------------------
__device__ float d_grouped[(size_t)NTOT*6];          // 12.6 MB
__device__ float d_y[(size_t)NTOT*64];               // 134 MB (y1, then in-place y2)
__device__ float d_mx[(size_t)BB*SS*128];            // 8 MB
__device__ float d_mn[(size_t)BB*SS*128];            // 8 MB
__device__ float d_ps1[64*4096],  d_pq1[64*4096];
__device__ float d_ps2[64*4096],  d_pq2[64*4096];
__device__ float d_ps3[128*8192], d_pq3[128*8192];
__device__ float d_nmean[3][128];
__device__ float d_nscale[3][128];
__device__ float d_nbeta[3][128];
__device__ int   d_pad[8];

// ---------------- pad kernels: shift launch index so ncu -s 5 hits k_fps ----
__global__ void k_pad(int i) { if (threadIdx.x == 0) d_pad[i] = i; }

// ---------------- FPS: one block/batch, 256 thr, 16 pts/thr -----------------
// Per-point arithmetic identical to the passing R3 kernel (same dd values).
// Argmax: value-only fmaxf shuffle reduce; index by ballot (lane order =
// index order), lowest-index tie-break preserved; cross-warp via 64-bit key.
__global__ void __launch_bounds__(256,1) k_fps(const float* __restrict__ xyz,
                                               float* __restrict__ out) {
    int b = blockIdx.x;
    int tid = threadIdx.x;
    int lane = tid & 31, wid = tid >> 5;
    const float* X = xyz + (size_t)b * NN * 3;
    __shared__ ull skey[2][8];
    float px[16], py[16], pz[16], dd[16];
    int i0 = tid * 16;
    #pragma unroll
    for (int j = 0; j < 16; j++) {
        px[j] = X[(i0 + j) * 3 + 0];
        py[j] = X[(i0 + j) * 3 + 1];
        pz[j] = X[(i0 + j) * 3 + 2];
        dd[j] = 1e10f;
    }
    int w = 0;

    for (int it = 0; it < SS; it++) {
        float cx = __ldg(X + w * 3 + 0);
        float cy = __ldg(X + w * 3 + 1);
        float cz = __ldg(X + w * 3 + 2);
        if (tid == 0) {
            float* o = out + ((size_t)b * SS + it) * 3;
            o[0] = cx; o[1] = cy; o[2] = cz;
        }
        if (it == SS - 1) break;

        float bv = -1.0f;
        #pragma unroll
        for (int j = 0; j < 16; j++) {
            float dx = px[j] - cx, dy = py[j] - cy, dz = pz[j] - cz;
            float d = dx*dx + dy*dy + dz*dz;
            dd[j] = fminf(dd[j], d);
            bv = fmaxf(bv, dd[j]);
        }
        // local lowest-index match (independent of the shuffle chain -> overlaps)
        int li = 0;
        #pragma unroll
        for (int j = 15; j >= 0; j--) if (dd[j] == bv) li = i0 + j;
        // warp max of value only (32-bit FMNMX shuffles)
        float wv = bv;
        #pragma unroll
        for (int off = 16; off; off >>= 1)
            wv = fmaxf(wv, __shfl_xor_sync(0xffffffffu, wv, off));
        unsigned msk = __ballot_sync(0xffffffffu, bv == wv);
        int src = __ffs(msk) - 1;                // lowest lane = lowest index range
        int wli = __shfl_sync(0xffffffffu, li, src);
        ull key = ((ull)__float_as_uint(wv) << 32) | (unsigned)(0xFFFF - wli);
        if (lane == 0) skey[it & 1][wid] = key;
        __syncthreads();
        ull k0 = skey[it & 1][0];
        #pragma unroll
        for (int wq = 1; wq < 8; wq++) { ull o = skey[it & 1][wq]; k0 = (o > k0) ? o : k0; }
        w = 0xFFFF - (int)(k0 & 0xFFFFFFFFull);
    }
}

// ---------------- ball query + grouping: one warp per centroid --------------
__global__ void k_group(const float* __restrict__ xyz,
                        const float* __restrict__ pts,
                        const float* __restrict__ nxyz) {
    int gw = (blockIdx.x * blockDim.x + threadIdx.x) >> 5;
    int lane = threadIdx.x & 31;
    if (gw >= BB * SS) return;
    int b = gw >> 10;
    const float* X = xyz + (size_t)b * NN * 3;
    const float* P = pts + (size_t)b * NN * 3;
    const float* c = nxyz + (size_t)gw * 3;
    float cx = c[0], cy = c[1], cz = c[2];
    float s2 = cx*cx + cy*cy + cz*cz;
    float* G = d_grouped + (size_t)gw * KK * 6;

    int count = 0, firstIdx = 0;
    bool haveFirst = false;
    for (int ch = 0; ch < NN / 32 && count < KK; ch++) {
        int pi = ch * 32 + lane;
        float x = X[pi*3], y = X[pi*3+1], z = X[pi*3+2];
        float d2 = x*x + y*y + z*z;
        float dt = cx*x + cy*y + cz*z;
        float sq = (s2 + d2) - 2.0f * dt;
        bool inside = !(sq > 0.04f);
        unsigned m = __ballot_sync(0xffffffffu, inside);
        if (!haveFirst && m) { firstIdx = ch * 32 + (__ffs(m) - 1); haveFirst = true; }
        int slot = count + __popc(m & ((1u << lane) - 1u));
        if (inside && slot < KK) {
            float* g = G + slot * 6;
            g[0] = x - cx; g[1] = y - cy; g[2] = z - cz;
            g[3] = P[pi*3]; g[4] = P[pi*3+1]; g[5] = P[pi*3+2];
        }
        count += __popc(m);
    }
    if (count < KK) {
        int fi = firstIdx;
        float x = X[fi*3], y = X[fi*3+1], z = X[fi*3+2];
        float p0 = P[fi*3], p1 = P[fi*3+1], p2 = P[fi*3+2];
        for (int slot = count + lane; slot < KK; slot += 32) {
            float* g = G + slot * 6;
            g[0] = x - cx; g[1] = y - cy; g[2] = z - cz;
            g[3] = p0; g[4] = p1; g[5] = p2;
        }
    }
}

// ---------------- layer 1: 6 -> 64 ------------------------------------------
__global__ void k_layer1(const float* __restrict__ W, const float* __restrict__ Bv) {
    __shared__ __align__(16) float sin_[128 * 6];
    __shared__ float rs[256], rq[256];
    size_t pos0 = (size_t)blockIdx.x * 128;
    int tid = threadIdx.x;
    for (int t = tid; t < 128 * 6; t += 256) sin_[t] = d_grouped[pos0 * 6 + t];
    int c = tid & 63, g = tid >> 6;
    float w[6];
    #pragma unroll
    for (int i = 0; i < 6; i++) w[i] = W[c * 6 + i];
    float bb = Bv[c];
    __syncthreads();
    float ls = 0.f, lq = 0.f;
    for (int p = g; p < 128; p += 4) {
        float acc = bb;
        #pragma unroll
        for (int i = 0; i < 6; i++) acc += w[i] * sin_[p * 6 + i];
        d_y[(pos0 + p) * 64 + c] = acc;
        ls += acc; lq += acc * acc;
    }
    rs[tid] = ls; rq[tid] = lq;
    __syncthreads();
    if (tid < 64) {
        float S = rs[tid] + rs[tid+64] + rs[tid+128] + rs[tid+192];
        float Q = rq[tid] + rq[tid+64] + rq[tid+128] + rq[tid+192];
        d_ps1[tid * 4096 + blockIdx.x] = S;
        d_pq1[tid * 4096 + blockIdx.x] = Q;
    }
}

// ---------------- finalize: reduce partials, build norm params ---------------
__global__ void k_finalize(int layer, int nblk,
                           const float* __restrict__ gamma,
                           const float* __restrict__ beta) {
    const float* ps = layer == 0 ? d_ps1 : layer == 1 ? d_ps2 : d_ps3;
    const float* pq = layer == 0 ? d_pq1 : layer == 1 ? d_pq2 : d_pq3;
    int c = blockIdx.x;
    __shared__ double sd[256], sq[256];
    double s = 0.0, q = 0.0;
    for (int i = threadIdx.x; i < nblk; i += 256) {
        s += (double)ps[(size_t)c * nblk + i];
        q += (double)pq[(size_t)c * nblk + i];
    }
    sd[threadIdx.x] = s; sq[threadIdx.x] = q;
    __syncthreads();
    for (int off = 128; off; off >>= 1) {
        if (threadIdx.x < off) {
            sd[threadIdx.x] += sd[threadIdx.x + off];
            sq[threadIdx.x] += sq[threadIdx.x + off];
        }
        __syncthreads();
    }
    if (threadIdx.x == 0) {
        double n = (double)NTOT;
        double mean = sd[0] / n;
        double var  = sq[0] / n - mean * mean;
        float rstd = rsqrtf((float)var + 1e-5f);
        d_nmean[layer][c]  = (float)mean;
        d_nscale[layer][c] = gamma[c] * rstd;
        d_nbeta[layer][c]  = beta[c];
    }
}

// ---------------- layer 2: 64 -> 64, FFMA2, pair-interleaved shared ---------
__global__ void __launch_bounds__(256,1) k_layer2(const float* __restrict__ W,
                                                  const float* __restrict__ Bv) {
    __shared__ __align__(16) float s[64 * 128];   // 32KB
    __shared__ float rs[256], rq[256];
    size_t pos0 = (size_t)blockIdx.x * 128;
    int tid = threadIdx.x;
    {
        int cin = tid & 63;
        float nm = d_nmean[0][cin], nsc = d_nscale[0][cin], nb = d_nbeta[0][cin];
        for (int t = tid; t < 128 * 64; t += 256) {
            int p = t >> 6;
            float v = d_y[pos0 * 64 + t];
            v = fmaxf((v - nm) * nsc + nb, 0.f);
            s[(p >> 1) * 128 + cin * 2 + (p & 1)] = v;
        }
    }
    int c = tid & 63, g = tid >> 6;
    ull w2[64];
    #pragma unroll
    for (int i = 0; i < 64; i++) { float wv = W[c * 64 + i]; w2[i] = pack2(wv, wv); }
    float bb = Bv[c];
    __syncthreads();
    float ls = 0.f, lq = 0.f;
    for (int q = g; q < 64; q += 4) {
        const ulonglong2* sp = (const ulonglong2*)(s + q * 128);
        ull acc_a = pack2(bb, bb), acc_b = pack2(0.f, 0.f);
        #pragma unroll
        for (int i = 0; i < 32; i++) {
            ulonglong2 v = sp[i];
            acc_a = fma2(w2[2*i],   v.x, acc_a);
            acc_b = fma2(w2[2*i+1], v.y, acc_b);
        }
        ull acc = add2(acc_a, acc_b);
        float lo, hi; unpack2(acc, lo, hi);
        d_y[(pos0 + 2*q)     * 64 + c] = lo;
        d_y[(pos0 + 2*q + 1) * 64 + c] = hi;
        ls += lo + hi; lq += lo*lo + hi*hi;
    }
    rs[tid] = ls; rq[tid] = lq;
    __syncthreads();
    if (tid < 64) {
        float S = rs[tid] + rs[tid+64] + rs[tid+128] + rs[tid+192];
        float Q = rq[tid] + rq[tid+64] + rq[tid+128] + rq[tid+192];
        d_ps2[tid * 4096 + blockIdx.x] = S;
        d_pq2[tid * 4096 + blockIdx.x] = Q;
    }
}

// ---------------- layer 3: 64 -> 128, FFMA2, fused max/min pool --------------
__global__ void __launch_bounds__(256,1) k_layer3(const float* __restrict__ W,
                                                  const float* __restrict__ Bv) {
    __shared__ __align__(16) float s[32 * 128];   // 16KB
    __shared__ float rs[256], rq[256];
    __shared__ float smx[2][2][128], smn[2][2][128];
    size_t pos0 = (size_t)blockIdx.x * 64;        // 2 centroids per block
    int tid = threadIdx.x;
    {
        int cin = tid & 63;
        float nm = d_nmean[1][cin], nsc = d_nscale[1][cin], nb = d_nbeta[1][cin];
        for (int t = tid; t < 64 * 64; t += 256) {
            int p = t >> 6;
            float v = d_y[pos0 * 64 + t];
            v = fmaxf((v - nm) * nsc + nb, 0.f);
            s[(p >> 1) * 128 + cin * 2 + (p & 1)] = v;
        }
    }
    int c = tid & 127, g = tid >> 7;
    ull w2[64];
    #pragma unroll
    for (int i = 0; i < 64; i++) { float wv = W[c * 64 + i]; w2[i] = pack2(wv, wv); }
    float bb = Bv[c];
    __syncthreads();
    float ls = 0.f, lq = 0.f;
    float mx0 = -INFINITY, mn0 = INFINITY, mx1 = -INFINITY, mn1 = INFINITY;
    for (int q = g; q < 32; q += 2) {
        const ulonglong2* sp = (const ulonglong2*)(s + q * 128);
        ull acc_a = pack2(bb, bb), acc_b = pack2(0.f, 0.f);
        #pragma unroll
        for (int i = 0; i < 32; i++) {
            ulonglong2 v = sp[i];
            acc_a = fma2(w2[2*i],   v.x, acc_a);
            acc_b = fma2(w2[2*i+1], v.y, acc_b);
        }
        ull acc = add2(acc_a, acc_b);
        float lo, hi; unpack2(acc, lo, hi);
        ls += lo + hi; lq += lo*lo + hi*hi;
        float M = fmaxf(lo, hi), m = fminf(lo, hi);
        if (q < 16) { mx0 = fmaxf(mx0, M); mn0 = fminf(mn0, m); }
        else        { mx1 = fmaxf(mx1, M); mn1 = fminf(mn1, m); }
    }
    smx[g][0][c] = mx0; smx[g][1][c] = mx1;
    smn[g][0][c] = mn0; smn[g][1][c] = mn1;
    rs[tid] = ls; rq[tid] = lq;
    __syncthreads();
    {
        int cent = tid >> 7, cc = tid & 127;
        float M = fmaxf(smx[0][cent][cc], smx[1][cent][cc]);
        float m = fminf(smn[0][cent][cc], smn[1][cent][cc]);
        size_t o = (size_t)(blockIdx.x * 2 + cent) * 128 + cc;
        d_mx[o] = M; d_mn[o] = m;
    }
    if (tid < 128) {
        float S = rs[tid] + rs[tid + 128];
        float Q = rq[tid] + rq[tid + 128];
        d_ps3[tid * 8192 + blockIdx.x] = S;
        d_pq3[tid * 8192 + blockIdx.x] = Q;
    }
}

// ---------------- final pool: norm(max-or-min) + relu, write output ----------
__global__ void k_poolf(float* __restrict__ out) {
    int g = blockIdx.x * 256 + threadIdx.x;
    int c = g & 127;
    float scv = d_nscale[2][c];
    float v = (scv >= 0.f) ? d_mx[g] : d_mn[g];
    out[(size_t)BB * SS * 3 + g] = fmaxf((v - d_nmean[2][c]) * scv + d_nbeta[2][c], 0.f);
}

// ---------------- launch -----------------------------------------------------
extern "C" void kernel_launch(void* const* d_in, const int* in_sizes, int n_in,
                              void* d_out, int out_size) {
    const float* xyz = (const float*)d_in[0];
    const float* pts = (const float*)d_in[1];
    const float* w0  = (const float*)d_in[2];
    const float* b0  = (const float*)d_in[3];
    const float* g0  = (const float*)d_in[4];
    const float* be0 = (const float*)d_in[5];
    const float* w1  = (const float*)d_in[6];
    const float* b1  = (const float*)d_in[7];
    const float* g1  = (const float*)d_in[8];
    const float* be1 = (const float*)d_in[9];
    const float* w2  = (const float*)d_in[10];
    const float* b2  = (const float*)d_in[11];
    const float* g2  = (const float*)d_in[12];
    const float* be2 = (const float*)d_in[13];
    float* out = (float*)d_out;

    // pads 0..4 so ncu (-s 5 -c 1) profiles k_fps as launch #5
    for (int i = 0; i < 5; i++) k_pad<<<1, 32>>>(i);
    k_fps<<<BB, 256>>>(xyz, out);
    k_group<<<(BB * SS) / 8, 256>>>(xyz, pts, out);
    k_layer1<<<NTOT / 128, 256>>>(w0, b0);
    k_finalize<<<64, 256>>>(0, 4096, g0, be0);
    k_layer2<<<NTOT / 128, 256>>>(w1, b1);
    k_finalize<<<64, 256>>>(1, 4096, g1, be1);
    k_layer3<<<NTOT / 64, 256>>>(w2, b2);
    k_finalize<<<128, 256>>>(2, 8192, g2, be2);
    k_poolf<<<(BB * SS * 128) / 256, 256>>>(out);
}

// round 7
// speedup vs baseline: 1.3174x; 1.0509x over previous
#include <cuda_runtime.h>
#include <math.h>

#define BB 16
#define NN 4096
#define SS 1024
#define KK 32
#define NTOT (BB*SS*KK)   /* 524288 positions */

typedef unsigned long long ull;

// ---- packed f32x2 helpers (Blackwell FFMA2 path) ---------------------------
__device__ __forceinline__ ull pack2(float lo, float hi) {
    ull r; asm("mov.b64 %0, {%1, %2};" : "=l"(r) : "f"(lo), "f"(hi)); return r;
}
__device__ __forceinline__ void unpack2(ull v, float& lo, float& hi) {
    asm("mov.b64 {%0, %1}, %2;" : "=f"(lo), "=f"(hi) : "l"(v));
}
__device__ __forceinline__ ull fma2(ull a, ull b, ull c) {
    ull d; asm("fma.rn.f32x2 %0, %1, %2, %3;" : "=l"(d) : "l"(a), "l"(b), "l"(c)); return d;
}
__device__ __forceinline__ ull add2(ull a, ull b) {
    ull d; asm("add.rn.f32x2 %0, %1, %2;" : "=l"(d) : "l"(a), "l"(b)); return d;
}
__device__ __forceinline__ ull mul2(ull a, ull b) {
    ull d; asm("mul.rn.f32x2 %0, %1, %2;" : "=l"(d) : "l"(a), "l"(b)); return d;
}

// ---------------- scratch (static device globals) ---------------------------
__device__ float d_grouped[(size_t)NTOT*6];          // 12.6 MB
__device__ float d_y[(size_t)NTOT*64];               // 134 MB (y1, then in-place y2)
__device__ float d_mx[(size_t)BB*SS*128];            // 8 MB
__device__ float d_mn[(size_t)BB*SS*128];            // 8 MB
__device__ float d_ps1[64*4096],  d_pq1[64*4096];
__device__ float d_ps2[64*4096],  d_pq2[64*4096];
__device__ float d_ps3[128*8192], d_pq3[128*8192];
__device__ float d_nmean[3][128];
__device__ float d_nscale[3][128];
__device__ float d_nbeta[3][128];

// ---------------- FPS: one block/batch, 256 thr, 16 pts/thr -----------------
// Distance update in packed f32x2 with rounding order identical to the scalar
// version that passes (x+(-c) == x-c; mul,fma,fma left-to-right). Argmax with
// lowest-index tie-break via fmaxf-shuffle reduce + ballot; cross-warp via
// 64-bit key tree.
__global__ void __launch_bounds__(256,1) k_fps(const float* __restrict__ xyz,
                                               float* __restrict__ out) {
    int b = blockIdx.x;
    int tid = threadIdx.x;
    int lane = tid & 31, wid = tid >> 5;
    const float* X = xyz + (size_t)b * NN * 3;
    __shared__ ull skey[2][8];
    ull px2[8], py2[8], pz2[8];
    float dd[16];
    int i0 = tid * 16;
    #pragma unroll
    for (int i = 0; i < 8; i++) {
        int j0 = i0 + 2*i, j1 = i0 + 2*i + 1;
        px2[i] = pack2(X[j0*3+0], X[j1*3+0]);
        py2[i] = pack2(X[j0*3+1], X[j1*3+1]);
        pz2[i] = pack2(X[j0*3+2], X[j1*3+2]);
    }
    #pragma unroll
    for (int j = 0; j < 16; j++) dd[j] = 1e10f;
    int w = 0;

    for (int it = 0; it < SS; it++) {
        float cx = __ldg(X + w * 3 + 0);
        float cy = __ldg(X + w * 3 + 1);
        float cz = __ldg(X + w * 3 + 2);
        if (tid == 0) {
            float* o = out + ((size_t)b * SS + it) * 3;
            o[0] = cx; o[1] = cy; o[2] = cz;
        }
        if (it == SS - 1) break;

        ull ncx = pack2(-cx, -cx), ncy = pack2(-cy, -cy), ncz = pack2(-cz, -cz);
        #pragma unroll
        for (int i = 0; i < 8; i++) {
            ull dx = add2(px2[i], ncx);          // px - cx (IEEE identical)
            ull dy = add2(py2[i], ncy);
            ull dz = add2(pz2[i], ncz);
            ull t  = mul2(dx, dx);               // dx*dx
            t = fma2(dy, dy, t);                 // + dy*dy
            t = fma2(dz, dz, t);                 // + dz*dz
            float d0, d1; unpack2(t, d0, d1);
            dd[2*i]   = fminf(dd[2*i],   d0);
            dd[2*i+1] = fminf(dd[2*i+1], d1);
        }
        // tree max over 16 (depth 4)
        float m[8];
        #pragma unroll
        for (int i = 0; i < 8; i++) m[i] = fmaxf(dd[2*i], dd[2*i+1]);
        float m0 = fmaxf(fmaxf(m[0], m[1]), fmaxf(m[2], m[3]));
        float m1 = fmaxf(fmaxf(m[4], m[5]), fmaxf(m[6], m[7]));
        float bv = fmaxf(m0, m1);
        // local lowest-index match
        int li = 0;
        #pragma unroll
        for (int j = 15; j >= 0; j--) if (dd[j] == bv) li = i0 + j;
        // warp max of value only (32-bit FMNMX shuffles)
        float wv = bv;
        #pragma unroll
        for (int off = 16; off; off >>= 1)
            wv = fmaxf(wv, __shfl_xor_sync(0xffffffffu, wv, off));
        unsigned msk = __ballot_sync(0xffffffffu, bv == wv);
        int src = __ffs(msk) - 1;                // lowest lane = lowest index range
        int wli = __shfl_sync(0xffffffffu, li, src);
        ull key = ((ull)__float_as_uint(wv) << 32) | (unsigned)(0xFFFF - wli);
        if (lane == 0) skey[it & 1][wid] = key;
        __syncthreads();
        const ull* sk = skey[it & 1];
        ull a0 = sk[0] > sk[1] ? sk[0] : sk[1];
        ull a1 = sk[2] > sk[3] ? sk[2] : sk[3];
        ull a2 = sk[4] > sk[5] ? sk[4] : sk[5];
        ull a3 = sk[6] > sk[7] ? sk[6] : sk[7];
        ull b0 = a0 > a1 ? a0 : a1;
        ull b1 = a2 > a3 ? a2 : a3;
        ull k0 = b0 > b1 ? b0 : b1;
        w = 0xFFFF - (int)(k0 & 0xFFFFFFFFull);
    }
}

// ---------------- ball query + grouping: one warp per centroid --------------
// Early-exit checked every 4 chunks so chunk loads pipeline (MLP 4+).
__global__ void k_group(const float* __restrict__ xyz,
                        const float* __restrict__ pts,
                        const float* __restrict__ nxyz) {
    int gw = (blockIdx.x * blockDim.x + threadIdx.x) >> 5;
    int lane = threadIdx.x & 31;
    if (gw >= BB * SS) return;
    int b = gw >> 10;
    const float* X = xyz + (size_t)b * NN * 3;
    const float* P = pts + (size_t)b * NN * 3;
    const float* c = nxyz + (size_t)gw * 3;
    float cx = c[0], cy = c[1], cz = c[2];
    float s2 = cx*cx + cy*cy + cz*cz;
    float* G = d_grouped + (size_t)gw * KK * 6;

    int count = 0, firstIdx = 0;
    bool haveFirst = false;
    for (int c4 = 0; c4 < NN / 128 && count < KK; c4++) {
        #pragma unroll
        for (int s = 0; s < 4; s++) {
            int pi = (c4 * 4 + s) * 32 + lane;
            float x = X[pi*3], y = X[pi*3+1], z = X[pi*3+2];
            float d2 = x*x + y*y + z*z;
            float dt = cx*x + cy*y + cz*z;
            float sq = (s2 + d2) - 2.0f * dt;
            bool inside = !(sq > 0.04f);
            unsigned m = __ballot_sync(0xffffffffu, inside);
            if (!haveFirst && m) { firstIdx = (c4*4+s)*32 + (__ffs(m) - 1); haveFirst = true; }
            int slot = count + __popc(m & ((1u << lane) - 1u));
            if (inside && slot < KK) {
                float* g = G + slot * 6;
                g[0] = x - cx; g[1] = y - cy; g[2] = z - cz;
                g[3] = P[pi*3]; g[4] = P[pi*3+1]; g[5] = P[pi*3+2];
            }
            count += __popc(m);
        }
    }
    if (count < KK) {
        int fi = firstIdx;
        float x = X[fi*3], y = X[fi*3+1], z = X[fi*3+2];
        float p0 = P[fi*3], p1 = P[fi*3+1], p2 = P[fi*3+2];
        for (int slot = count + lane; slot < KK; slot += 32) {
            float* g = G + slot * 6;
            g[0] = x - cx; g[1] = y - cy; g[2] = z - cz;
            g[3] = p0; g[4] = p1; g[5] = p2;
        }
    }
}

// ---------------- layer 1: 6 -> 64 ------------------------------------------
__global__ void k_layer1(const float* __restrict__ W, const float* __restrict__ Bv) {
    __shared__ __align__(16) float sin_[128 * 6];
    __shared__ float rs[256], rq[256];
    size_t pos0 = (size_t)blockIdx.x * 128;
    int tid = threadIdx.x;
    if (tid < 192) {
        float4 v = ((const float4*)(d_grouped + pos0 * 6))[tid];
        ((float4*)sin_)[tid] = v;
    }
    int c = tid & 63, g = tid >> 6;
    float w[6];
    #pragma unroll
    for (int i = 0; i < 6; i++) w[i] = W[c * 6 + i];
    float bb = Bv[c];
    __syncthreads();
    float ls = 0.f, lq = 0.f;
    for (int p = g; p < 128; p += 4) {
        float acc = bb;
        #pragma unroll
        for (int i = 0; i < 6; i++) acc += w[i] * sin_[p * 6 + i];
        d_y[(pos0 + p) * 64 + c] = acc;
        ls += acc; lq += acc * acc;
    }
    rs[tid] = ls; rq[tid] = lq;
    __syncthreads();
    if (tid < 64) {
        float S = rs[tid] + rs[tid+64] + rs[tid+128] + rs[tid+192];
        float Q = rq[tid] + rq[tid+64] + rq[tid+128] + rq[tid+192];
        d_ps1[tid * 4096 + blockIdx.x] = S;
        d_pq1[tid * 4096 + blockIdx.x] = Q;
    }
}

// ---------------- finalize: reduce partials, build norm params ---------------
__global__ void k_finalize(int layer, int nblk,
                           const float* __restrict__ gamma,
                           const float* __restrict__ beta) {
    const float* ps = layer == 0 ? d_ps1 : layer == 1 ? d_ps2 : d_ps3;
    const float* pq = layer == 0 ? d_pq1 : layer == 1 ? d_pq2 : d_pq3;
    int c = blockIdx.x;
    __shared__ double sd[256], sq[256];
    double s = 0.0, q = 0.0;
    const float4* ps4 = (const float4*)(ps + (size_t)c * nblk);
    const float4* pq4 = (const float4*)(pq + (size_t)c * nblk);
    for (int i = threadIdx.x; i < nblk / 4; i += 256) {
        float4 a = ps4[i], bq = pq4[i];
        s += (double)a.x + a.y + a.z + a.w;
        q += (double)bq.x + bq.y + bq.z + bq.w;
    }
    sd[threadIdx.x] = s; sq[threadIdx.x] = q;
    __syncthreads();
    for (int off = 128; off; off >>= 1) {
        if (threadIdx.x < off) {
            sd[threadIdx.x] += sd[threadIdx.x + off];
            sq[threadIdx.x] += sq[threadIdx.x + off];
        }
        __syncthreads();
    }
    if (threadIdx.x == 0) {
        double n = (double)NTOT;
        double mean = sd[0] / n;
        double var  = sq[0] / n - mean * mean;
        float rstd = rsqrtf((float)var + 1e-5f);
        d_nmean[layer][c]  = (float)mean;
        d_nscale[layer][c] = gamma[c] * rstd;
        d_nbeta[layer][c]  = beta[c];
    }
}

// ---------------- layer 2: 64 -> 64, FFMA2, pair-interleaved shared ---------
__global__ void __launch_bounds__(256,1) k_layer2(const float* __restrict__ W,
                                                  const float* __restrict__ Bv) {
    __shared__ __align__(16) float s[64 * 128];   // 32KB
    __shared__ float rs[256], rq[256];
    size_t pos0 = (size_t)blockIdx.x * 128;
    int tid = threadIdx.x;
    {
        int cin0 = (tid & 15) * 4;                // constant across iterations
        float nm0 = d_nmean[0][cin0],   sc0 = d_nscale[0][cin0],   nb0 = d_nbeta[0][cin0];
        float nm1 = d_nmean[0][cin0+1], sc1 = d_nscale[0][cin0+1], nb1 = d_nbeta[0][cin0+1];
        float nm2 = d_nmean[0][cin0+2], sc2 = d_nscale[0][cin0+2], nb2 = d_nbeta[0][cin0+2];
        float nm3 = d_nmean[0][cin0+3], sc3 = d_nscale[0][cin0+3], nb3 = d_nbeta[0][cin0+3];
        const float4* src = (const float4*)(d_y + pos0 * 64);
        for (int t4 = tid; t4 < 2048; t4 += 256) {
            float4 v = src[t4];
            int p = t4 >> 4;
            float* dst = s + (p >> 1) * 128 + (p & 1) + cin0 * 2;
            dst[0] = fmaxf((v.x - nm0) * sc0 + nb0, 0.f);
            dst[2] = fmaxf((v.y - nm1) * sc1 + nb1, 0.f);
            dst[4] = fmaxf((v.z - nm2) * sc2 + nb2, 0.f);
            dst[6] = fmaxf((v.w - nm3) * sc3 + nb3, 0.f);
        }
    }
    int c = tid & 63, g = tid >> 6;
    ull w2[64];
    #pragma unroll
    for (int i = 0; i < 64; i++) { float wv = W[c * 64 + i]; w2[i] = pack2(wv, wv); }
    float bb = Bv[c];
    __syncthreads();
    float ls = 0.f, lq = 0.f;
    for (int q = g; q < 64; q += 4) {
        const ulonglong2* sp = (const ulonglong2*)(s + q * 128);
        ull acc_a = pack2(bb, bb), acc_b = pack2(0.f, 0.f);
        #pragma unroll
        for (int i = 0; i < 32; i++) {
            ulonglong2 v = sp[i];
            acc_a = fma2(w2[2*i],   v.x, acc_a);
            acc_b = fma2(w2[2*i+1], v.y, acc_b);
        }
        ull acc = add2(acc_a, acc_b);
        float lo, hi; unpack2(acc, lo, hi);
        d_y[(pos0 + 2*q)     * 64 + c] = lo;
        d_y[(pos0 + 2*q + 1) * 64 + c] = hi;
        ls += lo + hi; lq += lo*lo + hi*hi;
    }
    rs[tid] = ls; rq[tid] = lq;
    __syncthreads();
    if (tid < 64) {
        float S = rs[tid] + rs[tid+64] + rs[tid+128] + rs[tid+192];
        float Q = rq[tid] + rq[tid+64] + rq[tid+128] + rq[tid+192];
        d_ps2[tid * 4096 + blockIdx.x] = S;
        d_pq2[tid * 4096 + blockIdx.x] = Q;
    }
}

// ---------------- layer 3: 64 -> 128, FFMA2, fused max/min pool --------------
__global__ void __launch_bounds__(256,1) k_layer3(const float* __restrict__ W,
                                                  const float* __restrict__ Bv) {
    __shared__ __align__(16) float s[32 * 128];   // 16KB
    __shared__ float rs[256], rq[256];
    __shared__ float smx[2][2][128], smn[2][2][128];
    size_t pos0 = (size_t)blockIdx.x * 64;        // 2 centroids per block
    int tid = threadIdx.x;
    {
        int cin0 = (tid & 15) * 4;
        float nm0 = d_nmean[1][cin0],   sc0 = d_nscale[1][cin0],   nb0 = d_nbeta[1][cin0];
        float nm1 = d_nmean[1][cin0+1], sc1 = d_nscale[1][cin0+1], nb1 = d_nbeta[1][cin0+1];
        float nm2 = d_nmean[1][cin0+2], sc2 = d_nscale[1][cin0+2], nb2 = d_nbeta[1][cin0+2];
        float nm3 = d_nmean[1][cin0+3], sc3 = d_nscale[1][cin0+3], nb3 = d_nbeta[1][cin0+3];
        const float4* src = (const float4*)(d_y + pos0 * 64);
        for (int t4 = tid; t4 < 1024; t4 += 256) {
            float4 v = src[t4];
            int p = t4 >> 4;
            float* dst = s + (p >> 1) * 128 + (p & 1) + cin0 * 2;
            dst[0] = fmaxf((v.x - nm0) * sc0 + nb0, 0.f);
            dst[2] = fmaxf((v.y - nm1) * sc1 + nb1, 0.f);
            dst[4] = fmaxf((v.z - nm2) * sc2 + nb2, 0.f);
            dst[6] = fmaxf((v.w - nm3) * sc3 + nb3, 0.f);
        }
    }
    int c = tid & 127, g = tid >> 7;
    ull w2[64];
    #pragma unroll
    for (int i = 0; i < 64; i++) { float wv = W[c * 64 + i]; w2[i] = pack2(wv, wv); }
    float bb = Bv[c];
    __syncthreads();
    float ls = 0.f, lq = 0.f;
    float mx0 = -INFINITY, mn0 = INFINITY, mx1 = -INFINITY, mn1 = INFINITY;
    for (int q = g; q < 32; q += 2) {
        const ulonglong2* sp = (const ulonglong2*)(s + q * 128);
        ull acc_a = pack2(bb, bb), acc_b = pack2(0.f, 0.f);
        #pragma unroll
        for (int i = 0; i < 32; i++) {
            ulonglong2 v = sp[i];
            acc_a = fma2(w2[2*i],   v.x, acc_a);
            acc_b = fma2(w2[2*i+1], v.y, acc_b);
        }
        ull acc = add2(acc_a, acc_b);
        float lo, hi; unpack2(acc, lo, hi);
        ls += lo + hi; lq += lo*lo + hi*hi;
        float M = fmaxf(lo, hi), m = fminf(lo, hi);
        if (q < 16) { mx0 = fmaxf(mx0, M); mn0 = fminf(mn0, m); }
        else        { mx1 = fmaxf(mx1, M); mn1 = fminf(mn1, m); }
    }
    smx[g][0][c] = mx0; smx[g][1][c] = mx1;
    smn[g][0][c] = mn0; smn[g][1][c] = mn1;
    rs[tid] = ls; rq[tid] = lq;
    __syncthreads();
    {
        int cent = tid >> 7, cc = tid & 127;
        float M = fmaxf(smx[0][cent][cc], smx[1][cent][cc]);
        float m = fminf(smn[0][cent][cc], smn[1][cent][cc]);
        size_t o = (size_t)(blockIdx.x * 2 + cent) * 128 + cc;
        d_mx[o] = M; d_mn[o] = m;
    }
    if (tid < 128) {
        float S = rs[tid] + rs[tid + 128];
        float Q = rq[tid] + rq[tid + 128];
        d_ps3[tid * 8192 + blockIdx.x] = S;
        d_pq3[tid * 8192 + blockIdx.x] = Q;
    }
}

// ---------------- final pool: norm(max-or-min) + relu, write output ----------
__global__ void k_poolf(float* __restrict__ out) {
    int g = blockIdx.x * 256 + threadIdx.x;
    int c = g & 127;
    float scv = d_nscale[2][c];
    float v = (scv >= 0.f) ? d_mx[g] : d_mn[g];
    out[(size_t)BB * SS * 3 + g] = fmaxf((v - d_nmean[2][c]) * scv + d_nbeta[2][c], 0.f);
}

// ---------------- launch -----------------------------------------------------
extern "C" void kernel_launch(void* const* d_in, const int* in_sizes, int n_in,
                              void* d_out, int out_size) {
    const float* xyz = (const float*)d_in[0];
    const float* pts = (const float*)d_in[1];
    const float* w0  = (const float*)d_in[2];
    const float* b0  = (const float*)d_in[3];
    const float* g0  = (const float*)d_in[4];
    const float* be0 = (const float*)d_in[5];
    const float* w1  = (const float*)d_in[6];
    const float* b1  = (const float*)d_in[7];
    const float* g1  = (const float*)d_in[8];
    const float* be1 = (const float*)d_in[9];
    const float* w2  = (const float*)d_in[10];
    const float* b2  = (const float*)d_in[11];
    const float* g2  = (const float*)d_in[12];
    const float* be2 = (const float*)d_in[13];
    float* out = (float*)d_out;

    k_fps<<<BB, 256>>>(xyz, out);
    k_group<<<(BB * SS) / 8, 256>>>(xyz, pts, out);
    k_layer1<<<NTOT / 128, 256>>>(w0, b0);
    k_finalize<<<64, 256>>>(0, 4096, g0, be0);
    k_layer2<<<NTOT / 128, 256>>>(w1, b1);
    k_finalize<<<64, 256>>>(1, 4096, g1, be1);
    k_layer3<<<NTOT / 64, 256>>>(w2, b2);
    k_finalize<<<128, 256>>>(2, 8192, g2, be2);
    k_poolf<<<(BB * SS * 128) / 256, 256>>>(out);
}